// round 5
// baseline (speedup 1.0000x reference)
#include <cuda_runtime.h>
#include <math.h>

// Problem shape (fixed by the dataset)
#define BB 4
#define NN 2048
#define CC 3
#define MM 4096          // NN * (CC-1) candidates per image
#define NW 64            // MM/64 mask words per row
#define MAXDET 100

#define SCORE_THR 0.05f
#define NMS_THR   0.5f
#define MIN_SIZE  0.01f

// ---------------- device scratch (static; no allocation APIs) ----------------
__device__ unsigned long long g_keys[BB][MM];
__device__ float4 g_boxes[BB][MM];
__device__ float  g_sc[BB][MM];
__device__ float4 g_sb[BB][MM];    // sorted boxes (plain)
__device__ float4 g_sob[BB][MM];   // sorted boxes + class offset (for IoU)
__device__ float  g_ss[BB][MM];    // sorted scores
__device__ int    g_slab[BB][MM];  // sorted labels
__device__ int    g_V[BB];         // valid count per image
__device__ unsigned long long g_mask[BB][MM][NW];  // 8 MB suppression matrix (zero-init; lower-tri never written)

// Correctly-rounded f32 exp via double (and immune to fast-math)
__device__ __forceinline__ float exact_expf(float x) { return (float)exp((double)x); }

__device__ __forceinline__ float read_dim(const void* p) {
    if (p == nullptr) return 800.0f;
    int vi = *(const int*)p;
    if (vi > 0 && vi < 1000000) return (float)vi;
    float vf = *(const float*)p;
    return (vf > 0.0f && vf < 1.0e6f) ? vf : 800.0f;
}

// ---------------- K1: softmax + decode + clip + key build ----------------
__global__ void k1_decode(const float* __restrict__ logits,
                          const float* __restrict__ reg,
                          const float* __restrict__ props,
                          const void* hp, const void* wp)
{
    const float SCLAMP = 4.135166556742356f;  // log(1000/16) rounded to f32
    int t = blockIdx.x * blockDim.x + threadIdx.x;
    if (t >= BB * NN) return;
    int img = t >> 11;
    int n   = t & (NN - 1);

    float Hf = read_dim(hp);
    float Wf = read_dim(wp);

    // softmax over 3 logits (sub max, exp, / sum) — mirrors jax.nn.softmax
    const float* lg = logits + (size_t)(img * NN + n) * CC;
    float l0 = lg[0], l1 = lg[1], l2 = lg[2];
    float mxl = fmaxf(l0, fmaxf(l1, l2));
    float e0 = exact_expf(__fsub_rn(l0, mxl));
    float e1 = exact_expf(__fsub_rn(l1, mxl));
    float e2 = exact_expf(__fsub_rn(l2, mxl));
    float s  = __fadd_rn(__fadd_rn(e0, e1), e2);
    float scr[2];
    scr[0] = __fdiv_rn(e1, s);
    scr[1] = __fdiv_rn(e2, s);

    const float* pr = props + (size_t)(img * NN + n) * 4;
    float x1 = pr[0], y1 = pr[1], x2 = pr[2], y2 = pr[3];
    float w  = __fsub_rn(x2, x1);
    float h  = __fsub_rn(y2, y1);
    float cx = __fadd_rn(x1, __fmul_rn(0.5f, w));
    float cy = __fadd_rn(y1, __fmul_rn(0.5f, h));

    const float* rg = reg + (size_t)(img * NN + n) * (4 * CC);

    #pragma unroll
    for (int c = 1; c <= 2; ++c) {
        const float* r = rg + 4 * c;
        float dx = __fdiv_rn(r[0], 10.0f);
        float dy = __fdiv_rn(r[1], 10.0f);
        float dw = fminf(__fdiv_rn(r[2], 5.0f), SCLAMP);
        float dh = fminf(__fdiv_rn(r[3], 5.0f), SCLAMP);
        float pcx = __fadd_rn(__fmul_rn(dx, w), cx);
        float pcy = __fadd_rn(__fmul_rn(dy, h), cy);
        float pw  = __fmul_rn(exact_expf(dw), w);
        float ph  = __fmul_rn(exact_expf(dh), h);
        float bx1 = __fsub_rn(pcx, __fmul_rn(0.5f, pw));
        float by1 = __fsub_rn(pcy, __fmul_rn(0.5f, ph));
        float bx2 = __fadd_rn(pcx, __fmul_rn(0.5f, pw));
        float by2 = __fadd_rn(pcy, __fmul_rn(0.5f, ph));
        bx1 = fminf(fmaxf(bx1, 0.0f), Wf);
        by1 = fminf(fmaxf(by1, 0.0f), Hf);
        bx2 = fminf(fmaxf(bx2, 0.0f), Wf);
        by2 = fminf(fmaxf(by2, 0.0f), Hf);

        int m = n * 2 + (c - 1);
        g_boxes[img][m] = make_float4(bx1, by1, bx2, by2);
        float sc = scr[c - 1];
        g_sc[img][m] = sc;

        bool valid = (sc > SCORE_THR)
                  && (__fsub_rn(bx2, bx1) >= MIN_SIZE)
                  && (__fsub_rn(by2, by1) >= MIN_SIZE);
        unsigned scu = valid ? __float_as_uint(sc) : 0u;  // positive floats: bits monotonic
        g_keys[img][m] = (((unsigned long long)(0x7FFFFFFFu - scu)) << 12) | (unsigned)m;
    }
}

// ---------------- K2: per-image bitonic sort + gmax + gather ----------------
__global__ void k2_sort()
{
    __shared__ unsigned long long sk[MM];   // 32 KB
    __shared__ float sred[512];
    __shared__ int scnt;

    int img = blockIdx.x;
    int tid = threadIdx.x;

    for (int i = tid; i < MM; i += 512) sk[i] = g_keys[img][i];

    // max box coordinate (all >= 0 after clip)
    float mx = 0.0f;
    for (int i = tid; i < MM; i += 512) {
        float4 b = g_boxes[img][i];
        mx = fmaxf(mx, fmaxf(fmaxf(b.x, b.y), fmaxf(b.z, b.w)));
    }
    sred[tid] = mx;
    __syncthreads();
    #pragma unroll
    for (int s = 256; s > 0; s >>= 1) {
        if (tid < s) sred[tid] = fmaxf(sred[tid], sred[tid + s]);
        __syncthreads();
    }
    float base_off = __fadd_rn(sred[0], 1.0f);

    // bitonic sort, ascending (key = descending score, stable by index)
    for (int k = 2; k <= MM; k <<= 1) {
        for (int j = k >> 1; j > 0; j >>= 1) {
            __syncthreads();
            for (int i = tid; i < MM; i += 512) {
                int l = i ^ j;
                if (l > i) {
                    unsigned long long a = sk[i], b = sk[l];
                    bool up = ((i & k) == 0);
                    if ((a > b) == up) { sk[i] = b; sk[l] = a; }
                }
            }
        }
    }
    __syncthreads();

    if (tid == 0) scnt = 0;
    __syncthreads();

    int local = 0;
    for (int i = tid; i < MM; i += 512) {
        unsigned long long key = sk[i];
        int m = (int)(key & 0xFFFull);
        if ((key >> 12) != 0x7FFFFFFFull) local++;
        float4 b = g_boxes[img][m];
        int lab = (m & 1) + 1;
        float off = __fmul_rn((float)lab, base_off);
        g_sb[img][i]  = b;
        g_sob[img][i] = make_float4(__fadd_rn(b.x, off), __fadd_rn(b.y, off),
                                    __fadd_rn(b.z, off), __fadd_rn(b.w, off));
        g_ss[img][i]   = g_sc[img][m];
        g_slab[img][i] = lab;
    }
    atomicAdd(&scnt, local);
    __syncthreads();
    if (tid == 0) g_V[img] = scnt;
}

// ---------------- K3: suppression bit-matrix (upper triangle only) ----------------
__global__ void k3_mask()
{
    int img = blockIdx.z, rc = blockIdx.y, cc = blockIdx.x;
    if (cc < rc) return;                       // strictly-lower words never read (stay 0)
    int V = g_V[img];
    V = max(0, min(V, MM));
    if (rc * 64 >= V || cc * 64 >= V) return;  // beyond valid prefix never read (stay 0)

    __shared__ float4 cb[64];
    __shared__ float  ca[64];
    int t = threadIdx.x;

    float4 q = g_sob[img][cc * 64 + t];
    cb[t] = q;
    ca[t] = __fmul_rn(__fsub_rn(q.z, q.x), __fsub_rn(q.w, q.y));
    __syncthreads();

    int i = rc * 64 + t;
    float4 a = g_sob[img][i];
    float aa = __fmul_rn(__fsub_rn(a.z, a.x), __fsub_rn(a.w, a.y));

    unsigned long long bits = 0ull;
    int jstart = (cc == rc) ? (t + 1) : 0;
    for (int jj = jstart; jj < 64; ++jj) {
        float4 b = cb[jj];
        float lx = fmaxf(a.x, b.x), ly = fmaxf(a.y, b.y);
        float rx = fminf(a.z, b.z), ry = fminf(a.w, b.w);
        float wd = fmaxf(__fsub_rn(rx, lx), 0.0f);
        float hg = fmaxf(__fsub_rn(ry, ly), 0.0f);
        float inter = __fmul_rn(wd, hg);
        if (inter > 0.0f) {  // iou==0 can't exceed thr; skips the precise FDIV
            float den = __fadd_rn(__fsub_rn(__fadd_rn(aa, ca[jj]), inter), 1e-7f);
            if (__fdiv_rn(inter, den) > NMS_THR) bits |= (1ull << jj);
        }
    }
    g_mask[img][i][cc] = bits;
}

// ---------------- K4: single-warp CHUNKED greedy scan (no __syncthreads) ----------------
// Per 64-row chunk: remv word via one shuffle, diag-block words lane-distributed
// (prefetched one chunk ahead), ffsll jumps kept-row to kept-row (suppressed rows
// cost nothing), then one lane-parallel OR round updates future remv words.
__global__ void k4_scan(float* __restrict__ out)
{
    int img  = blockIdx.x;
    int lane = threadIdx.x;           // blockDim = 32
    int V = g_V[img];
    V = max(0, min(V, MM));
    int wmax = (V + 63) >> 6;

    __shared__ int kept[MAXDET];

    // remv bitset distributed: lane owns words {lane, lane+32}
    unsigned long long r0 = 0ull, r1 = 0ull;
    int cnt = 0;

    // diag-block words of chunk 0: lane holds word c of rows base+lane, base+lane+32
    unsigned long long d0 = 0ull, d1 = 0ull;
    if (wmax > 0) {
        if (lane      < V) d0 = g_mask[img][lane     ][0];
        if (lane + 32 < V) d1 = g_mask[img][lane + 32][0];
    }

    for (int c = 0; c < wmax && cnt < MAXDET; ++c) {
        int base = c << 6;

        // prefetch diag block of chunk c+1 (independent of this chunk's results)
        unsigned long long nd0 = 0ull, nd1 = 0ull;
        if (c + 1 < wmax) {
            int nb = base + 64;
            if (nb + lane      < V) nd0 = g_mask[img][nb + lane     ][c + 1];
            if (nb + lane + 32 < V) nd1 = g_mask[img][nb + lane + 32][c + 1];
        }

        // current remv word c (broadcast from owner lane; all-uniform)
        unsigned long long wsrc = (c & 32) ? r1 : r0;
        unsigned long long w = __shfl_sync(0xFFFFFFFFu, wsrc, c & 31);

        int nrows = min(64, V - base);
        unsigned long long avail = ~w;
        if (nrows < 64) avail &= ((1ull << nrows) - 1ull);

        // jump kept-row to kept-row; suppressed rows are skipped in O(1)
        unsigned long long km = 0ull;
        while (avail && cnt < MAXDET) {
            int k = __ffsll((long long)avail) - 1;        // uniform across warp
            unsigned long long rowd =
                __shfl_sync(0xFFFFFFFFu, (k & 32) ? d1 : d0, k & 31);
            if (lane == 0) kept[cnt] = base + k;
            cnt++;
            km |= (1ull << k);
            avail &= ~(1ull << k);
            avail &= ~rowd;                               // in-chunk suppression (word c, bits > k only)
        }

        // cross-chunk suppression: OR kept rows' words (c, wmax) into distributed remv
        if (km) {
            int w0 = lane, w1 = lane + 32;
            bool u0 = (w0 > c) && (w0 < wmax);
            bool u1 = (w1 > c) && (w1 < wmax);
            unsigned long long mm = km;
            while (mm) {
                int k = __ffsll((long long)mm) - 1;
                mm &= (mm - 1);
                if (u0) r0 |= g_mask[img][base + k][w0];
                if (u1) r1 |= g_mask[img][base + k][w1];
            }
        }

        d0 = nd0; d1 = nd1;
    }
    __syncwarp();

    // output layout (flatten-concat, all f32):
    // boxes [B,100,4] | scores [B,100] | labels [B,100] | keep [B,100]
    float* oB = out;
    float* oS = out + BB * MAXDET * 4;
    float* oL = oS + BB * MAXDET;
    float* oK = oL + BB * MAXDET;

    for (int r = lane; r < MAXDET; r += 32) {
        float4 bx = make_float4(0.f, 0.f, 0.f, 0.f);
        float sc = 0.f, lbf = 0.f, kp = 0.f;
        if (r < cnt) {
            int id = kept[r];
            bx  = g_sb[img][id];
            sc  = g_ss[img][id];
            lbf = (float)g_slab[img][id];
            kp  = 1.0f;
        }
        float* bptr = oB + (size_t)(img * MAXDET + r) * 4;
        bptr[0] = bx.x; bptr[1] = bx.y; bptr[2] = bx.z; bptr[3] = bx.w;
        oS[img * MAXDET + r] = sc;
        oL[img * MAXDET + r] = lbf;
        oK[img * MAXDET + r] = kp;
    }
}

// ---------------- launch ----------------
extern "C" void kernel_launch(void* const* d_in, const int* in_sizes, int n_in,
                              void* d_out, int out_size)
{
    const float* logits = (const float*)d_in[0];
    const float* reg    = (const float*)d_in[1];
    const float* props  = (const float*)d_in[2];
    const void*  hp     = (n_in > 3) ? d_in[3] : nullptr;
    const void*  wp     = (n_in > 4) ? d_in[4] : nullptr;
    float* out = (float*)d_out;

    k1_decode<<<(BB * NN + 255) / 256, 256>>>(logits, reg, props, hp, wp);
    k2_sort<<<BB, 512>>>();
    dim3 g3(64, 64, BB);
    k3_mask<<<g3, 64>>>();
    k4_scan<<<BB, 32>>>(out);
}

// round 15
// speedup vs baseline: 1.2729x; 1.2729x over previous
#include <cuda_runtime.h>
#include <math.h>

// Problem shape (fixed by the dataset)
#define BB 4
#define NN 2048
#define CC 3
#define MM 4096          // NN * (CC-1) candidates per image
#define NW 64            // MM/64 mask words per row
#define MAXDET 100
#define NTRI 2080        // 64*65/2 upper-triangle 64x64 tiles

#define SCORE_THR 0.05f
#define NMS_THR   0.5f
#define MIN_SIZE  0.01f

// ---------------- device scratch (static; no allocation APIs) ----------------
__device__ unsigned long long g_keys[BB][MM];
__device__ float4 g_boxes[BB][MM];
__device__ float  g_sc[BB][MM];
__device__ float4 g_sb[BB][MM];    // sorted boxes (plain)
__device__ float4 g_sob[BB][MM];   // sorted boxes + class offset (for IoU)
__device__ float  g_ss[BB][MM];    // sorted scores
__device__ int    g_slab[BB][MM];  // sorted labels
__device__ int    g_V[BB];         // valid count per image
__device__ unsigned long long g_mask[BB][MM][NW];  // 8 MB suppression matrix (zero-init; lower-tri never written)

// Correctly-rounded f32 exp via double (and immune to fast-math)
__device__ __forceinline__ float exact_expf(float x) { return (float)exp((double)x); }

__device__ __forceinline__ float read_dim(const void* p) {
    if (p == nullptr) return 800.0f;
    int vi = *(const int*)p;
    if (vi > 0 && vi < 1000000) return (float)vi;
    float vf = *(const float*)p;
    return (vf > 0.0f && vf < 1.0e6f) ? vf : 800.0f;
}

// ---------------- K1: softmax + decode + clip + key build ----------------
__global__ void k1_decode(const float* __restrict__ logits,
                          const float* __restrict__ reg,
                          const float* __restrict__ props,
                          const void* hp, const void* wp)
{
    const float SCLAMP = 4.135166556742356f;  // log(1000/16) rounded to f32
    int t = blockIdx.x * blockDim.x + threadIdx.x;
    if (t >= BB * NN) return;
    int img = t >> 11;
    int n   = t & (NN - 1);

    float Hf = read_dim(hp);
    float Wf = read_dim(wp);

    const float* lg = logits + (size_t)(img * NN + n) * CC;
    float l0 = lg[0], l1 = lg[1], l2 = lg[2];
    float mxl = fmaxf(l0, fmaxf(l1, l2));
    float e0 = exact_expf(__fsub_rn(l0, mxl));
    float e1 = exact_expf(__fsub_rn(l1, mxl));
    float e2 = exact_expf(__fsub_rn(l2, mxl));
    float s  = __fadd_rn(__fadd_rn(e0, e1), e2);
    float scr[2];
    scr[0] = __fdiv_rn(e1, s);
    scr[1] = __fdiv_rn(e2, s);

    const float* pr = props + (size_t)(img * NN + n) * 4;
    float x1 = pr[0], y1 = pr[1], x2 = pr[2], y2 = pr[3];
    float w  = __fsub_rn(x2, x1);
    float h  = __fsub_rn(y2, y1);
    float cx = __fadd_rn(x1, __fmul_rn(0.5f, w));
    float cy = __fadd_rn(y1, __fmul_rn(0.5f, h));

    const float* rg = reg + (size_t)(img * NN + n) * (4 * CC);

    #pragma unroll
    for (int c = 1; c <= 2; ++c) {
        const float* r = rg + 4 * c;
        float dx = __fdiv_rn(r[0], 10.0f);
        float dy = __fdiv_rn(r[1], 10.0f);
        float dw = fminf(__fdiv_rn(r[2], 5.0f), SCLAMP);
        float dh = fminf(__fdiv_rn(r[3], 5.0f), SCLAMP);
        float pcx = __fadd_rn(__fmul_rn(dx, w), cx);
        float pcy = __fadd_rn(__fmul_rn(dy, h), cy);
        float pw  = __fmul_rn(exact_expf(dw), w);
        float ph  = __fmul_rn(exact_expf(dh), h);
        float bx1 = __fsub_rn(pcx, __fmul_rn(0.5f, pw));
        float by1 = __fsub_rn(pcy, __fmul_rn(0.5f, ph));
        float bx2 = __fadd_rn(pcx, __fmul_rn(0.5f, pw));
        float by2 = __fadd_rn(pcy, __fmul_rn(0.5f, ph));
        bx1 = fminf(fmaxf(bx1, 0.0f), Wf);
        by1 = fminf(fmaxf(by1, 0.0f), Hf);
        bx2 = fminf(fmaxf(bx2, 0.0f), Wf);
        by2 = fminf(fmaxf(by2, 0.0f), Hf);

        int m = n * 2 + (c - 1);
        g_boxes[img][m] = make_float4(bx1, by1, bx2, by2);
        float sc = scr[c - 1];
        g_sc[img][m] = sc;

        bool valid = (sc > SCORE_THR)
                  && (__fsub_rn(bx2, bx1) >= MIN_SIZE)
                  && (__fsub_rn(by2, by1) >= MIN_SIZE);
        unsigned scu = valid ? __float_as_uint(sc) : 0u;  // positive floats: bits monotonic
        g_keys[img][m] = (((unsigned long long)(0x7FFFFFFFu - scu)) << 12) | (unsigned)m;
    }
}

// ---------------- K2: per-image bitonic sort (register-blocked) + gmax + gather ----------------
__device__ __forceinline__ void ce_reg(unsigned long long& a, unsigned long long& b, bool up) {
    // positions a-before-b; make ascending if up
    if ((a > b) == up) { unsigned long long t = a; a = b; b = t; }
}

__global__ void k2_sort()
{
    __shared__ unsigned long long sk[MM];   // 32 KB
    __shared__ float sred[512];
    __shared__ int scnt;

    int img = blockIdx.x;
    int tid = threadIdx.x;

    // ---- load blocked 8 elements into registers ----
    unsigned long long v[8];
    #pragma unroll
    for (int e = 0; e < 8; ++e) v[e] = g_keys[img][tid * 8 + e];

    // ---- intra-thread network: rounds k=2,4,8 entirely in registers ----
    // k=2 (j=1): dir by (off & 2)
    ce_reg(v[0], v[1], true);  ce_reg(v[2], v[3], false);
    ce_reg(v[4], v[5], true);  ce_reg(v[6], v[7], false);
    // k=4: j=2 then j=1, dir by (off & 4)
    ce_reg(v[0], v[2], true);  ce_reg(v[1], v[3], true);
    ce_reg(v[4], v[6], false); ce_reg(v[5], v[7], false);
    ce_reg(v[0], v[1], true);  ce_reg(v[2], v[3], true);
    ce_reg(v[4], v[5], false); ce_reg(v[6], v[7], false);
    // k=8: dir by (8*tid & 8) -> tid parity
    {
        bool u = ((tid & 1) == 0);
        ce_reg(v[0], v[4], u); ce_reg(v[1], v[5], u); ce_reg(v[2], v[6], u); ce_reg(v[3], v[7], u);
        ce_reg(v[0], v[2], u); ce_reg(v[1], v[3], u); ce_reg(v[4], v[6], u); ce_reg(v[5], v[7], u);
        ce_reg(v[0], v[1], u); ce_reg(v[2], v[3], u); ce_reg(v[4], v[5], u); ce_reg(v[6], v[7], u);
    }
    #pragma unroll
    for (int e = 0; e < 8; ++e) sk[tid * 8 + e] = v[e];

    // gmax reduction (overlaps with sort data already in smem)
    float mx = 0.0f;
    for (int i = tid; i < MM; i += 512) {
        float4 b = g_boxes[img][i];
        mx = fmaxf(mx, fmaxf(fmaxf(b.x, b.y), fmaxf(b.z, b.w)));
    }
    sred[tid] = mx;
    __syncthreads();
    #pragma unroll
    for (int s = 256; s > 0; s >>= 1) {
        if (tid < s) sred[tid] = fmaxf(sred[tid], sred[tid + s]);
        __syncthreads();
    }
    float base_off = __fadd_rn(sred[0], 1.0f);

    // ---- rounds k=16..4096: smem phases for j>=8, register tail for j=4,2,1 ----
    for (int k = 16; k <= MM; k <<= 1) {
        for (int j = k >> 1; j >= 8; j >>= 1) {
            for (int i = tid; i < MM; i += 512) {
                int l = i ^ j;
                if (l > i) {
                    unsigned long long a = sk[i], b = sk[l];
                    bool up = ((i & k) == 0);
                    if ((a > b) == up) { sk[i] = b; sk[l] = a; }
                }
            }
            __syncthreads();
        }
        // register tail: j=4,2,1 within this thread's 8-block, uniform dir
        bool u = (((tid * 8) & k) == 0);
        #pragma unroll
        for (int e = 0; e < 8; ++e) v[e] = sk[tid * 8 + e];
        ce_reg(v[0], v[4], u); ce_reg(v[1], v[5], u); ce_reg(v[2], v[6], u); ce_reg(v[3], v[7], u);
        ce_reg(v[0], v[2], u); ce_reg(v[1], v[3], u); ce_reg(v[4], v[6], u); ce_reg(v[5], v[7], u);
        ce_reg(v[0], v[1], u); ce_reg(v[2], v[3], u); ce_reg(v[4], v[5], u); ce_reg(v[6], v[7], u);
        #pragma unroll
        for (int e = 0; e < 8; ++e) sk[tid * 8 + e] = v[e];
        __syncthreads();
    }

    if (tid == 0) scnt = 0;
    __syncthreads();

    int local = 0;
    #pragma unroll
    for (int e = 0; e < 8; ++e) {
        int i = tid * 8 + e;
        unsigned long long key = sk[i];
        int m = (int)(key & 0xFFFull);
        if ((key >> 12) != 0x7FFFFFFFull) local++;
        float4 b = g_boxes[img][m];
        int lab = (m & 1) + 1;
        float off = __fmul_rn((float)lab, base_off);
        g_sb[img][i]  = b;
        g_sob[img][i] = make_float4(__fadd_rn(b.x, off), __fadd_rn(b.y, off),
                                    __fadd_rn(b.z, off), __fadd_rn(b.w, off));
        g_ss[img][i]   = g_sc[img][m];
        g_slab[img][i] = lab;
    }
    atomicAdd(&scnt, local);
    __syncthreads();
    if (tid == 0) g_V[img] = scnt;
}

// ---------------- K3: suppression bit-matrix, triangular grid ----------------
// blockIdx.x in [0, NTRI) maps to upper-triangle tile (rc <= cc):
// start(r) = r*(129-r)/2; rc from closed form + bounded fixup (integer-exact).
__global__ void k3_mask()
{
    int img = blockIdx.y;
    int t66 = blockIdx.x;

    int rc = (int)((129.0 - sqrt(129.0 * 129.0 - 8.0 * (double)t66)) * 0.5);
    rc = max(0, min(rc, 63));
    // fixup (at most a couple of iterations; bounds are hard)
    while (rc > 0 && (rc * (129 - rc)) / 2 > t66) --rc;
    while (rc < 63 && ((rc + 1) * (129 - (rc + 1))) / 2 <= t66) ++rc;
    int cc = rc + (t66 - (rc * (129 - rc)) / 2);

    int V = g_V[img];
    V = max(0, min(V, MM));
    if (rc * 64 >= V || cc * 64 >= V) return;  // beyond valid prefix never read (stay 0)

    __shared__ float4 cb[64];
    __shared__ float  ca[64];
    int t = threadIdx.x;

    float4 q = g_sob[img][cc * 64 + t];
    cb[t] = q;
    ca[t] = __fmul_rn(__fsub_rn(q.z, q.x), __fsub_rn(q.w, q.y));
    __syncthreads();

    int i = rc * 64 + t;
    float4 a = g_sob[img][i];
    float aa = __fmul_rn(__fsub_rn(a.z, a.x), __fsub_rn(a.w, a.y));

    unsigned long long bits = 0ull;
    int jstart = (cc == rc) ? (t + 1) : 0;
    for (int jj = jstart; jj < 64; ++jj) {
        float4 b = cb[jj];
        float lx = fmaxf(a.x, b.x), ly = fmaxf(a.y, b.y);
        float rx = fminf(a.z, b.z), ry = fminf(a.w, b.w);
        float wd = fmaxf(__fsub_rn(rx, lx), 0.0f);
        float hg = fmaxf(__fsub_rn(ry, ly), 0.0f);
        float inter = __fmul_rn(wd, hg);
        if (inter > 0.0f) {  // iou==0 can't exceed thr; skips the precise FDIV
            float den = __fadd_rn(__fsub_rn(__fadd_rn(aa, ca[jj]), inter), 1e-7f);
            if (__fdiv_rn(inter, den) > NMS_THR) bits |= (1ull << jj);
        }
    }
    g_mask[img][i][cc] = bits;
}

// ---------------- K4: single-warp greedy scan, 256-row chunks, smem diag block ----
// All lanes redundantly hold identical rw[4]/avail state: the keep-walk needs NO
// shuffles. Per chunk: one coalesced 8KB diag stage, uniform walk (per kept row:
// one broadcast LDS.128 pair), one MLP-overlapped cross-chunk OR round.
__global__ void k4_scan(float* __restrict__ out)
{
    __shared__ unsigned long long diag[256][4];   // 8 KB
    __shared__ int kept[MAXDET];

    int img  = blockIdx.x;
    int lane = threadIdx.x;           // blockDim = 32
    int V = g_V[img];
    V = max(0, min(V, MM));
    int wmax64 = (V + 63) >> 6;
    int wmax4  = (V + 255) >> 8;

    // remv bitset distributed: lane owns words {lane, lane+32}
    unsigned long long r0 = 0ull, r1 = 0ull;
    int cnt = 0;

    for (int c = 0; c < wmax4 && cnt < MAXDET; ++c) {
        int base = c << 8;

        // ---- stage diag block rows [base, base+256) x words [4c, 4c+4) ----
        #pragma unroll
        for (int rr = 0; rr < 8; ++rr) {
            int r = lane + (rr << 5);
            const uint4* src = (const uint4*)&g_mask[img][base + r][c << 2];
            uint4 a = src[0], b = src[1];
            *(uint4*)&diag[r][0] = a;
            *(uint4*)&diag[r][2] = b;
        }
        __syncwarp();

        // ---- fetch the 4 remv words for this chunk (uniform) ----
        unsigned long long rw[4];
        #pragma unroll
        for (int w = 0; w < 4; ++w) {
            int W = (c << 2) + w;
            unsigned long long src = (W & 32) ? r1 : r0;
            rw[w] = __shfl_sync(0xFFFFFFFFu, src, W & 31);
        }

        int cnt0 = cnt;
        // ---- uniform keep-walk over 4 sub-words ----
        #pragma unroll
        for (int w = 0; w < 4; ++w) {
            int wbase = base + (w << 6);
            int nb = V - wbase;
            if (nb <= 0) break;
            unsigned long long avail = ~rw[w];
            if (nb < 64) avail &= ((1ull << nb) - 1ull);
            while (avail && cnt < MAXDET) {
                int k = __ffsll((long long)avail) - 1;
                int lr = (w << 6) + k;                  // row within chunk
                if (lane == 0) kept[cnt] = wbase + k;
                cnt++;
                avail &= ~(1ull << k);
                unsigned long long d0 = diag[lr][0], d1 = diag[lr][1];
                unsigned long long d2 = diag[lr][2], d3 = diag[lr][3];
                rw[0] |= d0; rw[1] |= d1; rw[2] |= d2; rw[3] |= d3;
                avail &= ~((w == 0) ? d0 : (w == 1) ? d1 : (w == 2) ? d2 : d3);
            }
        }
        __syncwarp();

        // ---- cross-chunk OR: kept rows' words beyond this chunk into remv ----
        if (cnt > cnt0 && cnt < MAXDET) {
            int w0 = lane, w1 = lane + 32;
            bool u0 = (w0 > ((c << 2) + 3)) && (w0 < wmax64);
            bool u1 = (w1 > ((c << 2) + 3)) && (w1 < wmax64);
            for (int q = cnt0; q < cnt; ++q) {
                int g = kept[q];
                if (u0) r0 |= g_mask[img][g][w0];
                if (u1) r1 |= g_mask[img][g][w1];
            }
        }
        __syncwarp();
    }
    __syncwarp();

    // output layout (flatten-concat, all f32):
    // boxes [B,100,4] | scores [B,100] | labels [B,100] | keep [B,100]
    float* oB = out;
    float* oS = out + BB * MAXDET * 4;
    float* oL = oS + BB * MAXDET;
    float* oK = oL + BB * MAXDET;

    for (int r = lane; r < MAXDET; r += 32) {
        float4 bx = make_float4(0.f, 0.f, 0.f, 0.f);
        float sc = 0.f, lbf = 0.f, kp = 0.f;
        if (r < cnt) {
            int id = kept[r];
            bx  = g_sb[img][id];
            sc  = g_ss[img][id];
            lbf = (float)g_slab[img][id];
            kp  = 1.0f;
        }
        float* bptr = oB + (size_t)(img * MAXDET + r) * 4;
        bptr[0] = bx.x; bptr[1] = bx.y; bptr[2] = bx.z; bptr[3] = bx.w;
        oS[img * MAXDET + r] = sc;
        oL[img * MAXDET + r] = lbf;
        oK[img * MAXDET + r] = kp;
    }
}

// ---------------- launch ----------------
extern "C" void kernel_launch(void* const* d_in, const int* in_sizes, int n_in,
                              void* d_out, int out_size)
{
    const float* logits = (const float*)d_in[0];
    const float* reg    = (const float*)d_in[1];
    const float* props  = (const float*)d_in[2];
    const void*  hp     = (n_in > 3) ? d_in[3] : nullptr;
    const void*  wp     = (n_in > 4) ? d_in[4] : nullptr;
    float* out = (float*)d_out;

    k1_decode<<<(BB * NN + 255) / 256, 256>>>(logits, reg, props, hp, wp);
    k2_sort<<<BB, 512>>>();
    dim3 g3(NTRI, BB);
    k3_mask<<<g3, 64>>>();
    k4_scan<<<BB, 32>>>(out);
}

// round 17
// speedup vs baseline: 1.2981x; 1.0198x over previous
#include <cuda_runtime.h>
#include <math.h>

// Problem shape (fixed by the dataset)
#define BB 4
#define NN 2048
#define CC 3
#define MM 4096          // NN * (CC-1) candidates per image
#define NW 64            // MM/64 mask words per row
#define MAXDET 100
#define NTRI 2080        // 64*65/2 upper-triangle 64x64 tiles

#define SCORE_THR 0.05f
#define NMS_THR   0.5f
#define MIN_SIZE  0.01f

// padded smem index: one u64 pad per 8 elements -> conflict-free blocked LDS.64
#define PADI(i) ((i) + ((i) >> 3))

// ---------------- device scratch (static; no allocation APIs) ----------------
__device__ unsigned long long g_keys[BB][MM];
__device__ float4 g_boxes[BB][MM];
__device__ float  g_sc[BB][MM];
__device__ float4 g_sb[BB][MM];    // sorted boxes (plain)
__device__ float4 g_sob[BB][MM];   // sorted boxes + class offset (for IoU)
__device__ float  g_ss[BB][MM];    // sorted scores
__device__ int    g_slab[BB][MM];  // sorted labels
__device__ int    g_V[BB];         // valid count per image
__device__ unsigned long long g_mask[BB][MM][NW];  // 8 MB suppression matrix (zero-init; lower-tri never written)

// Correctly-rounded f32 exp via double (and immune to fast-math)
__device__ __forceinline__ float exact_expf(float x) { return (float)exp((double)x); }

__device__ __forceinline__ float read_dim(const void* p) {
    if (p == nullptr) return 800.0f;
    int vi = *(const int*)p;
    if (vi > 0 && vi < 1000000) return (float)vi;
    float vf = *(const float*)p;
    return (vf > 0.0f && vf < 1.0e6f) ? vf : 800.0f;
}

// ---------------- K1: softmax + decode + clip + key build ----------------
__global__ void k1_decode(const float* __restrict__ logits,
                          const float* __restrict__ reg,
                          const float* __restrict__ props,
                          const void* hp, const void* wp)
{
    const float SCLAMP = 4.135166556742356f;  // log(1000/16) rounded to f32
    int t = blockIdx.x * blockDim.x + threadIdx.x;
    if (t >= BB * NN) return;
    int img = t >> 11;
    int n   = t & (NN - 1);

    float Hf = read_dim(hp);
    float Wf = read_dim(wp);

    const float* lg = logits + (size_t)(img * NN + n) * CC;
    float l0 = lg[0], l1 = lg[1], l2 = lg[2];
    float mxl = fmaxf(l0, fmaxf(l1, l2));
    float e0 = exact_expf(__fsub_rn(l0, mxl));
    float e1 = exact_expf(__fsub_rn(l1, mxl));
    float e2 = exact_expf(__fsub_rn(l2, mxl));
    float s  = __fadd_rn(__fadd_rn(e0, e1), e2);
    float scr[2];
    scr[0] = __fdiv_rn(e1, s);
    scr[1] = __fdiv_rn(e2, s);

    const float* pr = props + (size_t)(img * NN + n) * 4;
    float x1 = pr[0], y1 = pr[1], x2 = pr[2], y2 = pr[3];
    float w  = __fsub_rn(x2, x1);
    float h  = __fsub_rn(y2, y1);
    float cx = __fadd_rn(x1, __fmul_rn(0.5f, w));
    float cy = __fadd_rn(y1, __fmul_rn(0.5f, h));

    const float* rg = reg + (size_t)(img * NN + n) * (4 * CC);

    #pragma unroll
    for (int c = 1; c <= 2; ++c) {
        const float* r = rg + 4 * c;
        float dx = __fdiv_rn(r[0], 10.0f);
        float dy = __fdiv_rn(r[1], 10.0f);
        float dw = fminf(__fdiv_rn(r[2], 5.0f), SCLAMP);
        float dh = fminf(__fdiv_rn(r[3], 5.0f), SCLAMP);
        float pcx = __fadd_rn(__fmul_rn(dx, w), cx);
        float pcy = __fadd_rn(__fmul_rn(dy, h), cy);
        float pw  = __fmul_rn(exact_expf(dw), w);
        float ph  = __fmul_rn(exact_expf(dh), h);
        float bx1 = __fsub_rn(pcx, __fmul_rn(0.5f, pw));
        float by1 = __fsub_rn(pcy, __fmul_rn(0.5f, ph));
        float bx2 = __fadd_rn(pcx, __fmul_rn(0.5f, pw));
        float by2 = __fadd_rn(pcy, __fmul_rn(0.5f, ph));
        bx1 = fminf(fmaxf(bx1, 0.0f), Wf);
        by1 = fminf(fmaxf(by1, 0.0f), Hf);
        bx2 = fminf(fmaxf(bx2, 0.0f), Wf);
        by2 = fminf(fmaxf(by2, 0.0f), Hf);

        int m = n * 2 + (c - 1);
        g_boxes[img][m] = make_float4(bx1, by1, bx2, by2);
        float sc = scr[c - 1];
        g_sc[img][m] = sc;

        bool valid = (sc > SCORE_THR)
                  && (__fsub_rn(bx2, bx1) >= MIN_SIZE)
                  && (__fsub_rn(by2, by1) >= MIN_SIZE);
        unsigned scu = valid ? __float_as_uint(sc) : 0u;  // positive floats: bits monotonic
        g_keys[img][m] = (((unsigned long long)(0x7FFFFFFFu - scu)) << 12) | (unsigned)m;
    }
}

// ---------------- K2: per-image bitonic sort (register-blocked, PADDED smem) ----------------
__device__ __forceinline__ void ce_reg(unsigned long long& a, unsigned long long& b, bool up) {
    // positions a-before-b; make ascending if up
    if ((a > b) == up) { unsigned long long t = a; a = b; b = t; }
}

__global__ void k2_sort()
{
    __shared__ unsigned long long sk[MM + (MM >> 3)];   // 36 KB padded
    __shared__ float sred[512];
    __shared__ int scnt;

    int img = blockIdx.x;
    int tid = threadIdx.x;

    // ---- load blocked 8 elements into registers ----
    unsigned long long v[8];
    #pragma unroll
    for (int e = 0; e < 8; ++e) v[e] = g_keys[img][tid * 8 + e];

    // ---- intra-thread network: rounds k=2,4,8 entirely in registers ----
    ce_reg(v[0], v[1], true);  ce_reg(v[2], v[3], false);
    ce_reg(v[4], v[5], true);  ce_reg(v[6], v[7], false);
    ce_reg(v[0], v[2], true);  ce_reg(v[1], v[3], true);
    ce_reg(v[4], v[6], false); ce_reg(v[5], v[7], false);
    ce_reg(v[0], v[1], true);  ce_reg(v[2], v[3], true);
    ce_reg(v[4], v[5], false); ce_reg(v[6], v[7], false);
    {
        bool u = ((tid & 1) == 0);
        ce_reg(v[0], v[4], u); ce_reg(v[1], v[5], u); ce_reg(v[2], v[6], u); ce_reg(v[3], v[7], u);
        ce_reg(v[0], v[2], u); ce_reg(v[1], v[3], u); ce_reg(v[4], v[6], u); ce_reg(v[5], v[7], u);
        ce_reg(v[0], v[1], u); ce_reg(v[2], v[3], u); ce_reg(v[4], v[5], u); ce_reg(v[6], v[7], u);
    }
    #pragma unroll
    for (int e = 0; e < 8; ++e) sk[PADI(tid * 8 + e)] = v[e];

    // gmax reduction (overlaps with sort data already in smem)
    float mx = 0.0f;
    for (int i = tid; i < MM; i += 512) {
        float4 b = g_boxes[img][i];
        mx = fmaxf(mx, fmaxf(fmaxf(b.x, b.y), fmaxf(b.z, b.w)));
    }
    sred[tid] = mx;
    __syncthreads();
    #pragma unroll
    for (int s = 256; s > 0; s >>= 1) {
        if (tid < s) sred[tid] = fmaxf(sred[tid], sred[tid + s]);
        __syncthreads();
    }
    float base_off = __fadd_rn(sred[0], 1.0f);

    // ---- rounds k=16..4096: smem phases for j>=8, register tail for j=4,2,1 ----
    for (int k = 16; k <= MM; k <<= 1) {
        for (int j = k >> 1; j >= 8; j >>= 1) {
            for (int i = tid; i < MM; i += 512) {
                int l = i ^ j;
                if (l > i) {
                    unsigned long long a = sk[PADI(i)], b = sk[PADI(l)];
                    bool up = ((i & k) == 0);
                    if ((a > b) == up) { sk[PADI(i)] = b; sk[PADI(l)] = a; }
                }
            }
            __syncthreads();
        }
        // register tail: j=4,2,1 within this thread's 8-block, uniform dir
        bool u = (((tid * 8) & k) == 0);
        #pragma unroll
        for (int e = 0; e < 8; ++e) v[e] = sk[PADI(tid * 8 + e)];
        ce_reg(v[0], v[4], u); ce_reg(v[1], v[5], u); ce_reg(v[2], v[6], u); ce_reg(v[3], v[7], u);
        ce_reg(v[0], v[2], u); ce_reg(v[1], v[3], u); ce_reg(v[4], v[6], u); ce_reg(v[5], v[7], u);
        ce_reg(v[0], v[1], u); ce_reg(v[2], v[3], u); ce_reg(v[4], v[5], u); ce_reg(v[6], v[7], u);
        #pragma unroll
        for (int e = 0; e < 8; ++e) sk[PADI(tid * 8 + e)] = v[e];
        __syncthreads();
    }

    if (tid == 0) scnt = 0;
    __syncthreads();

    int local = 0;
    #pragma unroll
    for (int e = 0; e < 8; ++e) {
        int i = tid * 8 + e;
        unsigned long long key = sk[PADI(i)];
        int m = (int)(key & 0xFFFull);
        if ((key >> 12) != 0x7FFFFFFFull) local++;
        float4 b = g_boxes[img][m];
        int lab = (m & 1) + 1;
        float off = __fmul_rn((float)lab, base_off);
        g_sb[img][i]  = b;
        g_sob[img][i] = make_float4(__fadd_rn(b.x, off), __fadd_rn(b.y, off),
                                    __fadd_rn(b.z, off), __fadd_rn(b.w, off));
        g_ss[img][i]   = g_sc[img][m];
        g_slab[img][i] = lab;
    }
    atomicAdd(&scnt, local);
    __syncthreads();
    if (tid == 0) g_V[img] = scnt;
}

// ---------------- K3: suppression bit-matrix, triangular grid ----------------
__global__ void k3_mask()
{
    int img = blockIdx.y;
    int t66 = blockIdx.x;

    int rc = (int)((129.0 - sqrt(129.0 * 129.0 - 8.0 * (double)t66)) * 0.5);
    rc = max(0, min(rc, 63));
    while (rc > 0 && (rc * (129 - rc)) / 2 > t66) --rc;
    while (rc < 63 && ((rc + 1) * (129 - (rc + 1))) / 2 <= t66) ++rc;
    int cc = rc + (t66 - (rc * (129 - rc)) / 2);

    int V = g_V[img];
    V = max(0, min(V, MM));
    if (rc * 64 >= V || cc * 64 >= V) return;

    __shared__ float4 cb[64];
    __shared__ float  ca[64];
    int t = threadIdx.x;

    float4 q = g_sob[img][cc * 64 + t];
    cb[t] = q;
    ca[t] = __fmul_rn(__fsub_rn(q.z, q.x), __fsub_rn(q.w, q.y));
    __syncthreads();

    int i = rc * 64 + t;
    float4 a = g_sob[img][i];
    float aa = __fmul_rn(__fsub_rn(a.z, a.x), __fsub_rn(a.w, a.y));

    unsigned long long bits = 0ull;
    int jstart = (cc == rc) ? (t + 1) : 0;
    for (int jj = jstart; jj < 64; ++jj) {
        float4 b = cb[jj];
        float lx = fmaxf(a.x, b.x), ly = fmaxf(a.y, b.y);
        float rx = fminf(a.z, b.z), ry = fminf(a.w, b.w);
        float wd = fmaxf(__fsub_rn(rx, lx), 0.0f);
        float hg = fmaxf(__fsub_rn(ry, ly), 0.0f);
        float inter = __fmul_rn(wd, hg);
        if (inter > 0.0f) {
            float den = __fadd_rn(__fsub_rn(__fadd_rn(aa, ca[jj]), inter), 1e-7f);
            if (__fdiv_rn(inter, den) > NMS_THR) bits |= (1ull << jj);
        }
    }
    g_mask[img][i][cc] = bits;
}

// ---------------- K4: single-warp greedy scan, 256-row chunks, smem diag block ----
__global__ void k4_scan(float* __restrict__ out)
{
    __shared__ unsigned long long diag[256][4];   // 8 KB
    __shared__ int kept[MAXDET];

    int img  = blockIdx.x;
    int lane = threadIdx.x;           // blockDim = 32
    int V = g_V[img];
    V = max(0, min(V, MM));
    int wmax64 = (V + 63) >> 6;
    int wmax4  = (V + 255) >> 8;

    unsigned long long r0 = 0ull, r1 = 0ull;
    int cnt = 0;

    for (int c = 0; c < wmax4 && cnt < MAXDET; ++c) {
        int base = c << 8;

        #pragma unroll
        for (int rr = 0; rr < 8; ++rr) {
            int r = lane + (rr << 5);
            const uint4* src = (const uint4*)&g_mask[img][base + r][c << 2];
            uint4 a = src[0], b = src[1];
            *(uint4*)&diag[r][0] = a;
            *(uint4*)&diag[r][2] = b;
        }
        __syncwarp();

        unsigned long long rw[4];
        #pragma unroll
        for (int w = 0; w < 4; ++w) {
            int W = (c << 2) + w;
            unsigned long long src = (W & 32) ? r1 : r0;
            rw[w] = __shfl_sync(0xFFFFFFFFu, src, W & 31);
        }

        int cnt0 = cnt;
        #pragma unroll
        for (int w = 0; w < 4; ++w) {
            int wbase = base + (w << 6);
            int nb = V - wbase;
            if (nb <= 0) break;
            unsigned long long avail = ~rw[w];
            if (nb < 64) avail &= ((1ull << nb) - 1ull);
            while (avail && cnt < MAXDET) {
                int k = __ffsll((long long)avail) - 1;
                int lr = (w << 6) + k;
                if (lane == 0) kept[cnt] = wbase + k;
                cnt++;
                avail &= ~(1ull << k);
                unsigned long long d0 = diag[lr][0], d1 = diag[lr][1];
                unsigned long long d2 = diag[lr][2], d3 = diag[lr][3];
                rw[0] |= d0; rw[1] |= d1; rw[2] |= d2; rw[3] |= d3;
                avail &= ~((w == 0) ? d0 : (w == 1) ? d1 : (w == 2) ? d2 : d3);
            }
        }
        __syncwarp();

        if (cnt > cnt0 && cnt < MAXDET) {
            int w0 = lane, w1 = lane + 32;
            bool u0 = (w0 > ((c << 2) + 3)) && (w0 < wmax64);
            bool u1 = (w1 > ((c << 2) + 3)) && (w1 < wmax64);
            for (int q = cnt0; q < cnt; ++q) {
                int g = kept[q];
                if (u0) r0 |= g_mask[img][g][w0];
                if (u1) r1 |= g_mask[img][g][w1];
            }
        }
        __syncwarp();
    }
    __syncwarp();

    // output layout (flatten-concat, all f32):
    // boxes [B,100,4] | scores [B,100] | labels [B,100] | keep [B,100]
    float* oB = out;
    float* oS = out + BB * MAXDET * 4;
    float* oL = oS + BB * MAXDET;
    float* oK = oL + BB * MAXDET;

    for (int r = lane; r < MAXDET; r += 32) {
        float4 bx = make_float4(0.f, 0.f, 0.f, 0.f);
        float sc = 0.f, lbf = 0.f, kp = 0.f;
        if (r < cnt) {
            int id = kept[r];
            bx  = g_sb[img][id];
            sc  = g_ss[img][id];
            lbf = (float)g_slab[img][id];
            kp  = 1.0f;
        }
        float* bptr = oB + (size_t)(img * MAXDET + r) * 4;
        bptr[0] = bx.x; bptr[1] = bx.y; bptr[2] = bx.z; bptr[3] = bx.w;
        oS[img * MAXDET + r] = sc;
        oL[img * MAXDET + r] = lbf;
        oK[img * MAXDET + r] = kp;
    }
}

// ---------------- launch ----------------
extern "C" void kernel_launch(void* const* d_in, const int* in_sizes, int n_in,
                              void* d_out, int out_size)
{
    const float* logits = (const float*)d_in[0];
    const float* reg    = (const float*)d_in[1];
    const float* props  = (const float*)d_in[2];
    const void*  hp     = (n_in > 3) ? d_in[3] : nullptr;
    const void*  wp     = (n_in > 4) ? d_in[4] : nullptr;
    float* out = (float*)d_out;

    k1_decode<<<(BB * NN + 255) / 256, 256>>>(logits, reg, props, hp, wp);
    k2_sort<<<BB, 512>>>();
    dim3 g3(NTRI, BB);
    k3_mask<<<g3, 64>>>();
    k4_scan<<<BB, 32>>>(out);
}